// round 4
// baseline (speedup 1.0000x reference)
#include <cuda_runtime.h>

#define NN    200
#define DD    128
#define BB    256
#define NH    4
#define DH    32
#define NL    2
#define FOUT  64
#define GDIM  64
#define NE    1600
#define ETOT  1800
#define ROWS  (NN*BB)          // 51200
#define NEGINF (-3.4e38f)

// ---------------- scratch (static device memory; no allocation) ----------------
__device__ float g_xt  [NN*BB*DD];        // activations [n][b][d]
__device__ float g_qkv [NN*BB*3*DD];
__device__ float g_attn[NN*BB*DD];
__device__ float g_t1  [NN*BB*DD];
__device__ float g_t2  [NN*BB*DD];
__device__ float g_feat[ROWS*FOUT];
__device__ float g_h   [ROWS*GDIM];
__device__ float g_as  [ROWS];
__device__ float g_ad  [ROWS];
__device__ float g_g   [ROWS*GDIM];
__device__ int   g_deg [NN+1];
__device__ int   g_off [NN+1];
__device__ int   g_srcs[ETOT];

// ---------------- transpose x[b][n][d] -> g_xt[n][b][d] ----------------
__global__ void k_transpose(const float* __restrict__ x) {
    int i = blockIdx.x * blockDim.x + threadIdx.x;
    if (i >= NN*BB*DD) return;
    int d = i & 127;
    int b = (i >> 7) & 255;
    int n = i >> 15;
    g_xt[i] = x[((b*NN + n) << 7) + d];
}

// ---------------- generic batched GEMM: C = A @ W^T (+bias) (+relu) ----------------
// A:[M,K] row-major, W:[N,K] row-major, C:[M,N]. M,N multiples of 64, K multiple of 16.
template<bool RELU, bool HASB>
__global__ __launch_bounds__(256) void k_gemm(
    const float* __restrict__ A, long long sA,
    const float* __restrict__ W, long long sW,
    const float* __restrict__ bias, long long sB,
    float* __restrict__ C, long long sC,
    int M, int N, int K)
{
    int z = blockIdx.z;
    A += (long long)z * sA;
    W += (long long)z * sW;
    C += (long long)z * sC;
    if (HASB) bias += (long long)z * sB;

    const int m0 = blockIdx.y * 64;
    const int n0 = blockIdx.x * 64;

    __shared__ float As[16][68];
    __shared__ float Bs[16][68];

    int tid = threadIdx.x;
    int tx = tid & 15, ty = tid >> 4;
    int lr = tid >> 2, lk = (tid & 3) * 4;

    float acc[4][4] = {};
    const float* Ap = A + (long long)(m0 + lr) * K + lk;
    const float* Wp = W + (long long)(n0 + lr) * K + lk;

    for (int k0 = 0; k0 < K; k0 += 16) {
        float4 a4 = *(const float4*)(Ap + k0);
        float4 b4 = *(const float4*)(Wp + k0);
        As[lk+0][lr] = a4.x; As[lk+1][lr] = a4.y; As[lk+2][lr] = a4.z; As[lk+3][lr] = a4.w;
        Bs[lk+0][lr] = b4.x; Bs[lk+1][lr] = b4.y; Bs[lk+2][lr] = b4.z; Bs[lk+3][lr] = b4.w;
        __syncthreads();
        #pragma unroll
        for (int kk = 0; kk < 16; kk++) {
            float ar[4], br[4];
            #pragma unroll
            for (int i = 0; i < 4; i++) ar[i] = As[kk][ty*4+i];
            #pragma unroll
            for (int j = 0; j < 4; j++) br[j] = Bs[kk][tx*4+j];
            #pragma unroll
            for (int i = 0; i < 4; i++)
                #pragma unroll
                for (int j = 0; j < 4; j++)
                    acc[i][j] = fmaf(ar[i], br[j], acc[i][j]);
        }
        __syncthreads();
    }
    #pragma unroll
    for (int i = 0; i < 4; i++) {
        int m = m0 + ty*4 + i;
        #pragma unroll
        for (int j = 0; j < 4; j++) {
            int n = n0 + tx*4 + j;
            float v = acc[i][j];
            if (HASB) v += bias[n];
            if (RELU) v = fmaxf(v, 0.f);
            C[(long long)m * N + n] = v;
        }
    }
}

// ---------------- fused attention per (head, node) ----------------
// one thread per query row (256 threads == S), K/V in smem, online softmax (chunk 8)
__global__ __launch_bounds__(256) void k_attn() {
    extern __shared__ float sm[];
    float* Ks = sm;               // [256][36]
    float* Vs = sm + 256*36;      // [256][36]

    int h = blockIdx.x, n = blockIdx.y;
    int tid = threadIdx.x;
    const float* base = g_qkv + (long long)n*BB*384 + (long long)tid*384 + h*DH;

    float q[32];
    #pragma unroll
    for (int d4 = 0; d4 < 8; d4++) {
        float4 qa = *(const float4*)(base + d4*4);
        q[d4*4+0] = qa.x; q[d4*4+1] = qa.y; q[d4*4+2] = qa.z; q[d4*4+3] = qa.w;
        float4 ka = *(const float4*)(base + 128 + d4*4);
        Ks[tid*36 + d4*4+0] = ka.x; Ks[tid*36 + d4*4+1] = ka.y;
        Ks[tid*36 + d4*4+2] = ka.z; Ks[tid*36 + d4*4+3] = ka.w;
        float4 va = *(const float4*)(base + 256 + d4*4);
        Vs[tid*36 + d4*4+0] = va.x; Vs[tid*36 + d4*4+1] = va.y;
        Vs[tid*36 + d4*4+2] = va.z; Vs[tid*36 + d4*4+3] = va.w;
    }
    __syncthreads();

    const float scale = 0.17677669529663687f;  // 1/sqrt(32)
    float m = NEGINF, ssum = 0.f;
    float o[32];
    #pragma unroll
    for (int d = 0; d < 32; d++) o[d] = 0.f;

    for (int k0 = 0; k0 < 256; k0 += 8) {
        float sc[8];
        #pragma unroll
        for (int kk = 0; kk < 8; kk++) {
            const float* Kr = Ks + (k0+kk)*36;
            float s = 0.f;
            #pragma unroll
            for (int d = 0; d < 32; d++) s = fmaf(q[d], Kr[d], s);
            sc[kk] = s * scale;
        }
        float cmax = sc[0];
        #pragma unroll
        for (int kk = 1; kk < 8; kk++) cmax = fmaxf(cmax, sc[kk]);
        float mn = fmaxf(m, cmax);
        float pc = __expf(m - mn);     // 0 when m == -inf
        ssum *= pc;
        #pragma unroll
        for (int d = 0; d < 32; d++) o[d] *= pc;
        #pragma unroll
        for (int kk = 0; kk < 8; kk++) {
            float p = __expf(sc[kk] - mn);
            ssum += p;
            const float* Vr = Vs + (k0+kk)*36;
            #pragma unroll
            for (int d = 0; d < 32; d++) o[d] = fmaf(p, Vr[d], o[d]);
        }
        m = mn;
    }

    float inv = 1.f / ssum;
    float* orow = g_attn + ((long long)n*BB + tid)*128 + h*DH;
    #pragma unroll
    for (int d4 = 0; d4 < 8; d4++) {
        float4 w;
        w.x = o[d4*4+0]*inv; w.y = o[d4*4+1]*inv;
        w.z = o[d4*4+2]*inv; w.w = o[d4*4+3]*inv;
        *(float4*)(orow + d4*4) = w;
    }
}

// ---------------- residual add + LayerNorm over D=128 (in place into x) ----------------
// gamma/beta already offset by layer; per-node stride = NL*DD
__global__ __launch_bounds__(128) void k_addln(
    float* __restrict__ x, const float* __restrict__ r,
    const float* __restrict__ gamma, const float* __restrict__ beta)
{
    int row = blockIdx.x;
    int n = row >> 8;
    int t = threadIdx.x;
    long long idx = (long long)row*128 + t;
    float v = x[idx] + r[idx];
    float s = v, s2 = v*v;
    #pragma unroll
    for (int o = 16; o; o >>= 1) {
        s  += __shfl_xor_sync(0xffffffffu, s,  o);
        s2 += __shfl_xor_sync(0xffffffffu, s2, o);
    }
    __shared__ float red[8];
    int w = t >> 5;
    if ((t & 31) == 0) { red[w] = s; red[4+w] = s2; }
    __syncthreads();
    s  = red[0]+red[1]+red[2]+red[3];
    s2 = red[4]+red[5]+red[6]+red[7];
    float mean = s * (1.f/128.f);
    float var  = s2 * (1.f/128.f) - mean*mean;
    float rinv = rsqrtf(var + 1e-5f);
    x[idx] = (v - mean) * rinv * gamma[n*(NL*DD) + t] + beta[n*(NL*DD) + t];
}

// ---------------- attention-coefficient dots: a_s/a_d per row ----------------
__global__ __launch_bounds__(256) void k_attdot(
    const float* __restrict__ asv, const float* __restrict__ adv)
{
    int w = threadIdx.x >> 5, lane = threadIdx.x & 31;
    int row = blockIdx.x*8 + w;
    const float* hr = g_h + (long long)row*GDIM;
    float h1 = hr[lane], h2 = hr[32+lane];
    float s = h1*asv[lane] + h2*asv[32+lane];
    float d = h1*adv[lane] + h2*adv[32+lane];
    #pragma unroll
    for (int o = 16; o; o >>= 1) {
        s += __shfl_xor_sync(0xffffffffu, s, o);
        d += __shfl_xor_sync(0xffffffffu, d, o);
    }
    if (lane == 0) { g_as[row] = s; g_ad[row] = d; }
}

// ---------------- CSR build (deterministic) ----------------
__global__ void k_zero() {
    int i = blockIdx.x*blockDim.x + threadIdx.x;
    if (i <= NN) g_deg[i] = 0;
}
__global__ void k_count(const int* __restrict__ ei) {
    int e = blockIdx.x*blockDim.x + threadIdx.x;
    if (e >= ETOT) return;
    int dst = (e < NE) ? ei[NE + e] : (e - NE);
    atomicAdd(&g_deg[dst], 1);
}
__global__ void k_scan() {
    __shared__ int s[256];
    int t = threadIdx.x;
    int v = (t < NN) ? g_deg[t] : 0;
    s[t] = v;
    __syncthreads();
    for (int o = 1; o < 256; o <<= 1) {
        int a = (t >= o) ? s[t-o] : 0;
        __syncthreads();
        s[t] += a;
        __syncthreads();
    }
    if (t < NN) g_off[t+1] = s[t];
    if (t == 0) g_off[0] = 0;
}
__global__ void k_scatter(const int* __restrict__ ei) {
    int e = blockIdx.x*blockDim.x + threadIdx.x;
    if (e >= ETOT) return;
    int dst = (e < NE) ? ei[NE + e] : (e - NE);
    int src = (e < NE) ? ei[e]      : (e - NE);
    int rank = 0;
    for (int j = 0; j < e; j++) {
        int dj = (j < NE) ? ei[NE + j] : (j - NE);
        if (dj == dst) rank++;
    }
    g_srcs[g_off[dst] + rank] = src;
}

// ---------------- GAT edge-softmax + aggregate: block per (dst n, batch b) ----------------
__global__ __launch_bounds__(64) void k_gat(const float* __restrict__ gatb) {
    int n = blockIdx.x, b = blockIdx.y;
    int off = g_off[n];
    int deg = g_off[n+1] - off;
    float ad = g_ad[b*NN + n];
    int tid = threadIdx.x, lane = tid & 31, w = tid >> 5;
    __shared__ float red[4];

    float lm = NEGINF;
    for (int i = tid; i < deg; i += 64) {
        int s = g_srcs[off + i];
        float e = g_as[b*NN + s] + ad;
        e = (e > 0.f) ? e : 0.2f*e;
        lm = fmaxf(lm, e);
    }
    #pragma unroll
    for (int o = 16; o; o >>= 1) lm = fmaxf(lm, __shfl_xor_sync(0xffffffffu, lm, o));
    if (lane == 0) red[w] = lm;
    __syncthreads();
    float mx = fmaxf(red[0], red[1]);

    float ls = 0.f;
    for (int i = tid; i < deg; i += 64) {
        int s = g_srcs[off + i];
        float e = g_as[b*NN + s] + ad;
        e = (e > 0.f) ? e : 0.2f*e;
        ls += __expf(e - mx);
    }
    #pragma unroll
    for (int o = 16; o; o >>= 1) ls += __shfl_xor_sync(0xffffffffu, ls, o);
    if (lane == 0) red[2 + w] = ls;
    __syncthreads();
    float denom = red[2] + red[3] + 1e-16f;

    // each thread = one feature
    float acc = 0.f;
    for (int i = 0; i < deg; i++) {
        int s = g_srcs[off + i];
        float e = g_as[b*NN + s] + ad;
        e = (e > 0.f) ? e : 0.2f*e;
        float wg = __expf(e - mx);
        acc = fmaf(wg, g_h[(long long)(b*NN + s)*GDIM + tid], acc);
    }
    g_g[(long long)(b*NN + n)*GDIM + tid] = acc / denom + gatb[tid];
}

// ---------------- predictor: warp per row, 2 outputs ----------------
__global__ __launch_bounds__(256) void k_pred(
    const float* __restrict__ pW, const float* __restrict__ pb, float* __restrict__ out)
{
    int w = threadIdx.x >> 5, lane = threadIdx.x & 31;
    int row = blockIdx.x*8 + w;
    const float* gr = g_g + (long long)row*GDIM;
    float a = gr[lane], c = gr[32+lane];
    float s0 = a*pW[lane]    + c*pW[32+lane];
    float s1 = a*pW[64+lane] + c*pW[96+lane];
    #pragma unroll
    for (int o = 16; o; o >>= 1) {
        s0 += __shfl_xor_sync(0xffffffffu, s0, o);
        s1 += __shfl_xor_sync(0xffffffffu, s1, o);
    }
    if (lane == 0) {
        out[row*2 + 0] = s0 + pb[0];
        out[row*2 + 1] = s1 + pb[1];
    }
}

// ---------------- host launcher ----------------
static void gemm(const float* A, long long sA, const float* W, long long sW,
                 const float* b, long long sB, float* C, long long sC,
                 int M, int N, int K, int batch, bool relu)
{
    dim3 grid(N/64, M/64, batch), block(256);
    if (relu)       k_gemm<true,  true ><<<grid, block>>>(A, sA, W, sW, b, sB, C, sC, M, N, K);
    else if (b)     k_gemm<false, true ><<<grid, block>>>(A, sA, W, sW, b, sB, C, sC, M, N, K);
    else            k_gemm<false, false><<<grid, block>>>(A, sA, W, sW, b, sB, C, sC, M, N, K);
}

extern "C" void kernel_launch(void* const* d_in, const int* in_sizes, int n_in,
                              void* d_out, int out_size)
{
    const float* x       = (const float*)d_in[0];
    const int*   ei      = (const int*)  d_in[1];
    const float* Wqkv    = (const float*)d_in[2];
    const float* bqkv    = (const float*)d_in[3];
    const float* Wo      = (const float*)d_in[4];
    const float* bo      = (const float*)d_in[5];
    const float* g1      = (const float*)d_in[6];
    const float* be1     = (const float*)d_in[7];
    const float* fW1     = (const float*)d_in[8];
    const float* fb1     = (const float*)d_in[9];
    const float* fW2     = (const float*)d_in[10];
    const float* fb2     = (const float*)d_in[11];
    const float* g2      = (const float*)d_in[12];
    const float* be2     = (const float*)d_in[13];
    const float* fcW     = (const float*)d_in[14];
    const float* fcb     = (const float*)d_in[15];
    const float* gatW    = (const float*)d_in[16];
    const float* att_src = (const float*)d_in[17];
    const float* att_dst = (const float*)d_in[18];
    const float* gatb    = (const float*)d_in[19];
    const float* predW   = (const float*)d_in[20];
    const float* predb   = (const float*)d_in[21];
    float* out = (float*)d_out;

    float *xt, *qkv, *attn, *t1, *t2, *feat, *hh;
    cudaGetSymbolAddress((void**)&xt,   g_xt);
    cudaGetSymbolAddress((void**)&qkv,  g_qkv);
    cudaGetSymbolAddress((void**)&attn, g_attn);
    cudaGetSymbolAddress((void**)&t1,   g_t1);
    cudaGetSymbolAddress((void**)&t2,   g_t2);
    cudaGetSymbolAddress((void**)&feat, g_feat);
    cudaGetSymbolAddress((void**)&hh,   g_h);

    const int ATT_SMEM = 2 * 256 * 36 * 4;   // 73728 B
    cudaFuncSetAttribute(k_attn, cudaFuncAttributeMaxDynamicSharedMemorySize, ATT_SMEM);

    k_transpose<<<(NN*BB*DD + 255)/256, 256>>>(x);

    for (int l = 0; l < NL; l++) {
        // QKV: [256,128] @ [384,128]^T per node
        gemm(xt, (long long)BB*DD,
             Wqkv + (long long)l*3*DD*DD, (long long)NL*3*DD*DD,
             bqkv + (long long)l*3*DD,    (long long)NL*3*DD,
             qkv, (long long)BB*3*DD,
             BB, 3*DD, DD, NN, false);
        // attention
        k_attn<<<dim3(NH, NN), 256, ATT_SMEM>>>();
        // output projection
        gemm(attn, (long long)BB*DD,
             Wo + (long long)l*DD*DD, (long long)NL*DD*DD,
             bo + (long long)l*DD,    (long long)NL*DD,
             t1, (long long)BB*DD,
             BB, DD, DD, NN, false);
        k_addln<<<ROWS, 128>>>(xt, t1, g1 + l*DD, be1 + l*DD);
        // FFN
        gemm(xt, (long long)BB*DD,
             fW1 + (long long)l*DD*DD, (long long)NL*DD*DD,
             fb1 + (long long)l*DD,    (long long)NL*DD,
             t2, (long long)BB*DD,
             BB, DD, DD, NN, true);
        gemm(t2, (long long)BB*DD,
             fW2 + (long long)l*DD*DD, (long long)NL*DD*DD,
             fb2 + (long long)l*DD,    (long long)NL*DD,
             t1, (long long)BB*DD,
             BB, DD, DD, NN, false);
        k_addln<<<ROWS, 128>>>(xt, t1, g2 + l*DD, be2 + l*DD);
    }

    // fc: flat [51200,128] @ [64,128]^T ; flat buffer is directly [B,N,64] after relabel
    gemm(xt, 0, fcW, 0, fcb, 0, feat, 0, ROWS, FOUT, DD, 1, false);
    // GAT linear: [51200,64] @ [64,64]^T (no bias)
    gemm(feat, 0, gatW, 0, nullptr, 0, hh, 0, ROWS, GDIM, FOUT, 1, false);

    k_attdot<<<ROWS/8, 256>>>(att_src, att_dst);

    k_zero<<<1, 256>>>();
    k_count<<<(ETOT + 255)/256, 256>>>(ei);
    k_scan<<<1, 256>>>();
    k_scatter<<<(ETOT + 255)/256, 256>>>(ei);

    k_gat<<<dim3(NN, BB), 64>>>(gatb);
    k_pred<<<ROWS/8, 256>>>(predW, predb, out);
}

// round 9
// speedup vs baseline: 1.3609x; 1.3609x over previous
#include <cuda_runtime.h>
#include <cuda_bf16.h>
#include <cstdint>

#define NN    200
#define DD    128
#define BB    256
#define NH    4
#define DH    32
#define NL    2
#define FOUT  64
#define GDIM  64
#define NE    1600
#define ETOT  1800
#define ROWS  (NN*BB)          // 51200
#define NEGINF (-3.4e38f)

// ---------------- scratch (static device memory; no allocation) ----------------
__device__ float g_xt  [NN*BB*DD];
__device__ float g_qkv [NN*BB*3*DD];
__device__ float g_attn[NN*BB*DD];
__device__ float g_t1  [NN*BB*DD];
__device__ float g_t2  [NN*BB*DD];
__device__ float g_feat[ROWS*FOUT];
__device__ float g_h   [ROWS*GDIM];
__device__ float g_as  [ROWS];
__device__ float g_ad  [ROWS];
__device__ float g_g   [ROWS*GDIM];
__device__ int   g_deg [NN+1];
__device__ int   g_off [NN+1];
__device__ int   g_srcs[ETOT];

__device__ __forceinline__ uint32_t smem_u32(const void* p) {
    uint32_t a;
    asm("{ .reg .u64 t; cvta.to.shared.u64 t, %1; cvt.u32.u64 %0, t; }" : "=r"(a) : "l"(p));
    return a;
}

// split one float4 into bf16 hi/lo pairs (packed 2x per u32)
__device__ __forceinline__ void cvt_split4(float4 v, uint2& hp, uint2& lp) {
    __nv_bfloat16 hx = __float2bfloat16(v.x), hy = __float2bfloat16(v.y);
    __nv_bfloat16 hz = __float2bfloat16(v.z), hw = __float2bfloat16(v.w);
    __nv_bfloat16 lx = __float2bfloat16(v.x - __bfloat162float(hx));
    __nv_bfloat16 ly = __float2bfloat16(v.y - __bfloat162float(hy));
    __nv_bfloat16 lz = __float2bfloat16(v.z - __bfloat162float(hz));
    __nv_bfloat16 lw = __float2bfloat16(v.w - __bfloat162float(hw));
    hp.x = ((uint32_t)__bfloat16_as_ushort(hy) << 16) | __bfloat16_as_ushort(hx);
    hp.y = ((uint32_t)__bfloat16_as_ushort(hw) << 16) | __bfloat16_as_ushort(hz);
    lp.x = ((uint32_t)__bfloat16_as_ushort(ly) << 16) | __bfloat16_as_ushort(lx);
    lp.y = ((uint32_t)__bfloat16_as_ushort(lw) << 16) | __bfloat16_as_ushort(lz);
}

// =================== HMMA GEMM: C[128 x 64 tile] = A @ W^T (+bias)(+relu) ===================
// A:[M,KK] fp32 row-major, W:[N,KK] fp32 row-major. bf16 2-term split, 3 accumulation passes.
// smem: Ah | Al | Wh | Wl, row stride KK+8 bf16 (16B aligned, ldmatrix conflict-free).
template<int KK, bool RELU, bool HASB>
__global__ __launch_bounds__(128) void k_mgemm(
    const float* __restrict__ A, long long sA,
    const float* __restrict__ W, long long sW,
    const float* __restrict__ bias, long long sB,
    float* __restrict__ C, long long sC, int N)
{
    constexpr int LDA = KK + 8;
    constexpr int K4 = KK / 4;

    extern __shared__ char sm[];
    __nv_bfloat16* Ah = (__nv_bfloat16*)sm;
    __nv_bfloat16* Al = Ah + 128 * LDA;
    __nv_bfloat16* Wh = Al + 128 * LDA;
    __nv_bfloat16* Wl = Wh + 64 * LDA;

    const int tid = threadIdx.x;
    const int bz = blockIdx.z;
    const int m0 = blockIdx.y * 128;
    const int n0 = blockIdx.x * 64;

    A += (long long)bz * sA;
    W += (long long)bz * sW;
    C += (long long)bz * sC;
    if (HASB) bias += (long long)bz * sB;

    // ---- load + convert A tile (128 x KK) ----
    {
        const float* Ag = A + (long long)m0 * KK;
        #pragma unroll
        for (int c = tid; c < 128 * K4; c += 128) {
            int row = c / K4, k4 = (c % K4) * 4;
            float4 v = *(const float4*)(Ag + (long long)row * KK + k4);
            uint2 hp, lp;
            cvt_split4(v, hp, lp);
            *(uint2*)&Ah[row * LDA + k4] = hp;
            *(uint2*)&Al[row * LDA + k4] = lp;
        }
    }
    // ---- load + convert W tile (64 x KK) ----
    {
        const float* Wg = W + (long long)n0 * KK;
        #pragma unroll
        for (int c = tid; c < 64 * K4; c += 128) {
            int row = c / K4, k4 = (c % K4) * 4;
            float4 v = *(const float4*)(Wg + (long long)row * KK + k4);
            uint2 hp, lp;
            cvt_split4(v, hp, lp);
            *(uint2*)&Wh[row * LDA + k4] = hp;
            *(uint2*)&Wl[row * LDA + k4] = lp;
        }
    }
    __syncthreads();

    const int wid = tid >> 5, lane = tid & 31;
    const int mw = wid * 32;

    float acc[2][8][4];
    #pragma unroll
    for (int t = 0; t < 2; t++)
        #pragma unroll
        for (int j = 0; j < 8; j++)
            #pragma unroll
            for (int q = 0; q < 4; q++) acc[t][j][q] = 0.f;

    uint32_t sAh = smem_u32(Ah), sAl = smem_u32(Al);
    uint32_t sWh = smem_u32(Wh), sWl = smem_u32(Wl);

    // per-lane ldmatrix source offsets
    const int a_row = lane & 15;            // rows r..r+15
    const int a_col = (lane >> 4) * 8;      // cols 0 / 8 within k16
    const int b_row = lane & 7;             // n rows 0..7
    const int b_col = ((lane >> 3) & 1) * 8;

    for (int pass = 0; pass < 3; pass++) {
        uint32_t sa = (pass == 2) ? sAl : sAh;
        uint32_t sw = (pass == 1) ? sWl : sWh;
        #pragma unroll
        for (int k0 = 0; k0 < KK; k0 += 16) {
            uint32_t a[2][4];
            #pragma unroll
            for (int t = 0; t < 2; t++) {
                uint32_t ad = sa + (uint32_t)(((mw + t*16 + a_row) * LDA + k0 + a_col) * 2);
                asm volatile("ldmatrix.sync.aligned.m8n8.x4.shared.b16 {%0,%1,%2,%3}, [%4];"
                    : "=r"(a[t][0]), "=r"(a[t][1]), "=r"(a[t][2]), "=r"(a[t][3]) : "r"(ad));
            }
            #pragma unroll
            for (int j = 0; j < 8; j++) {
                uint32_t bd = sw + (uint32_t)(((j*8 + b_row) * LDA + k0 + b_col) * 2);
                uint32_t b0, b1;
                asm volatile("ldmatrix.sync.aligned.m8n8.x2.shared.b16 {%0,%1}, [%2];"
                    : "=r"(b0), "=r"(b1) : "r"(bd));
                #pragma unroll
                for (int t = 0; t < 2; t++) {
                    asm volatile(
                        "mma.sync.aligned.m16n8k16.row.col.f32.bf16.bf16.f32 "
                        "{%0,%1,%2,%3}, {%4,%5,%6,%7}, {%8,%9}, {%0,%1,%2,%3};"
                        : "+f"(acc[t][j][0]), "+f"(acc[t][j][1]),
                          "+f"(acc[t][j][2]), "+f"(acc[t][j][3])
                        : "r"(a[t][0]), "r"(a[t][1]), "r"(a[t][2]), "r"(a[t][3]),
                          "r"(b0), "r"(b1));
                }
            }
        }
    }

    // ---- epilogue ----
    const int r0 = m0 + mw + (lane >> 2);
    const int nc = (lane & 3) * 2;
    #pragma unroll
    for (int j = 0; j < 8; j++) {
        int n = n0 + j*8 + nc;
        float b0v = 0.f, b1v = 0.f;
        if (HASB) { b0v = bias[n]; b1v = bias[n+1]; }
        #pragma unroll
        for (int t = 0; t < 2; t++) {
            float v0 = acc[t][j][0] + b0v, v1 = acc[t][j][1] + b1v;
            float v2 = acc[t][j][2] + b0v, v3 = acc[t][j][3] + b1v;
            if (RELU) {
                v0 = fmaxf(v0, 0.f); v1 = fmaxf(v1, 0.f);
                v2 = fmaxf(v2, 0.f); v3 = fmaxf(v3, 0.f);
            }
            long long r = r0 + t*16;
            float2 w0 = make_float2(v0, v1), w1 = make_float2(v2, v3);
            *(float2*)&C[r * N + n]       = w0;
            *(float2*)&C[(r + 8) * N + n] = w1;
        }
    }
}

// ---------------- transpose x[b][n][d] -> g_xt[n][b][d] ----------------
__global__ void k_transpose(const float* __restrict__ x) {
    int i = blockIdx.x * blockDim.x + threadIdx.x;
    if (i >= NN*BB*DD) return;
    int d = i & 127;
    int b = (i >> 7) & 255;
    int n = i >> 15;
    g_xt[i] = x[((b*NN + n) << 7) + d];
}

// ---------------- fused attention per (head, node) ----------------
__global__ __launch_bounds__(256) void k_attn() {
    extern __shared__ float smf[];
    float* Ks = smf;              // [256][36]
    float* Vs = smf + 256*36;     // [256][36]

    int h = blockIdx.x, n = blockIdx.y;
    int tid = threadIdx.x;
    const float* base = g_qkv + (long long)n*BB*384 + (long long)tid*384 + h*DH;

    float q[32];
    #pragma unroll
    for (int d4 = 0; d4 < 8; d4++) {
        float4 qa = *(const float4*)(base + d4*4);
        q[d4*4+0] = qa.x; q[d4*4+1] = qa.y; q[d4*4+2] = qa.z; q[d4*4+3] = qa.w;
        float4 ka = *(const float4*)(base + 128 + d4*4);
        Ks[tid*36 + d4*4+0] = ka.x; Ks[tid*36 + d4*4+1] = ka.y;
        Ks[tid*36 + d4*4+2] = ka.z; Ks[tid*36 + d4*4+3] = ka.w;
        float4 va = *(const float4*)(base + 256 + d4*4);
        Vs[tid*36 + d4*4+0] = va.x; Vs[tid*36 + d4*4+1] = va.y;
        Vs[tid*36 + d4*4+2] = va.z; Vs[tid*36 + d4*4+3] = va.w;
    }
    __syncthreads();

    const float scale = 0.17677669529663687f;
    float m = NEGINF, ssum = 0.f;
    float o[32];
    #pragma unroll
    for (int d = 0; d < 32; d++) o[d] = 0.f;

    for (int k0 = 0; k0 < 256; k0 += 8) {
        float sc[8];
        #pragma unroll
        for (int kk = 0; kk < 8; kk++) {
            const float* Kr = Ks + (k0+kk)*36;
            float s = 0.f;
            #pragma unroll
            for (int d = 0; d < 32; d++) s = fmaf(q[d], Kr[d], s);
            sc[kk] = s * scale;
        }
        float cmax = sc[0];
        #pragma unroll
        for (int kk = 1; kk < 8; kk++) cmax = fmaxf(cmax, sc[kk]);
        float mn = fmaxf(m, cmax);
        float pc = __expf(m - mn);
        ssum *= pc;
        #pragma unroll
        for (int d = 0; d < 32; d++) o[d] *= pc;
        #pragma unroll
        for (int kk = 0; kk < 8; kk++) {
            float p = __expf(sc[kk] - mn);
            ssum += p;
            const float* Vr = Vs + (k0+kk)*36;
            #pragma unroll
            for (int d = 0; d < 32; d++) o[d] = fmaf(p, Vr[d], o[d]);
        }
        m = mn;
    }

    float inv = 1.f / ssum;
    float* orow = g_attn + ((long long)n*BB + tid)*128 + h*DH;
    #pragma unroll
    for (int d4 = 0; d4 < 8; d4++) {
        float4 w;
        w.x = o[d4*4+0]*inv; w.y = o[d4*4+1]*inv;
        w.z = o[d4*4+2]*inv; w.w = o[d4*4+3]*inv;
        *(float4*)(orow + d4*4) = w;
    }
}

// ---------------- residual add + LayerNorm over D=128 ----------------
__global__ __launch_bounds__(128) void k_addln(
    float* __restrict__ x, const float* __restrict__ r,
    const float* __restrict__ gamma, const float* __restrict__ beta)
{
    int row = blockIdx.x;
    int n = row >> 8;
    int t = threadIdx.x;
    long long idx = (long long)row*128 + t;
    float v = x[idx] + r[idx];
    float s = v, s2 = v*v;
    #pragma unroll
    for (int o = 16; o; o >>= 1) {
        s  += __shfl_xor_sync(0xffffffffu, s,  o);
        s2 += __shfl_xor_sync(0xffffffffu, s2, o);
    }
    __shared__ float red[8];
    int w = t >> 5;
    if ((t & 31) == 0) { red[w] = s; red[4+w] = s2; }
    __syncthreads();
    s  = red[0]+red[1]+red[2]+red[3];
    s2 = red[4]+red[5]+red[6]+red[7];
    float mean = s * (1.f/128.f);
    float var  = s2 * (1.f/128.f) - mean*mean;
    float rinv = rsqrtf(var + 1e-5f);
    x[idx] = (v - mean) * rinv * gamma[n*(NL*DD) + t] + beta[n*(NL*DD) + t];
}

// ---------------- attention-coefficient dots ----------------
__global__ __launch_bounds__(256) void k_attdot(
    const float* __restrict__ asv, const float* __restrict__ adv)
{
    int w = threadIdx.x >> 5, lane = threadIdx.x & 31;
    int row = blockIdx.x*8 + w;
    const float* hr = g_h + (long long)row*GDIM;
    float h1 = hr[lane], h2 = hr[32+lane];
    float s = h1*asv[lane] + h2*asv[32+lane];
    float d = h1*adv[lane] + h2*adv[32+lane];
    #pragma unroll
    for (int o = 16; o; o >>= 1) {
        s += __shfl_xor_sync(0xffffffffu, s, o);
        d += __shfl_xor_sync(0xffffffffu, d, o);
    }
    if (lane == 0) { g_as[row] = s; g_ad[row] = d; }
}

// ---------------- CSR build (deterministic) ----------------
__global__ void k_zero() {
    int i = blockIdx.x*blockDim.x + threadIdx.x;
    if (i <= NN) g_deg[i] = 0;
}
__global__ void k_count(const int* __restrict__ ei) {
    int e = blockIdx.x*blockDim.x + threadIdx.x;
    if (e >= ETOT) return;
    int dst = (e < NE) ? ei[NE + e] : (e - NE);
    atomicAdd(&g_deg[dst], 1);
}
__global__ void k_scan() {
    __shared__ int s[256];
    int t = threadIdx.x;
    int v = (t < NN) ? g_deg[t] : 0;
    s[t] = v;
    __syncthreads();
    for (int o = 1; o < 256; o <<= 1) {
        int a = (t >= o) ? s[t-o] : 0;
        __syncthreads();
        s[t] += a;
        __syncthreads();
    }
    if (t < NN) g_off[t+1] = s[t];
    if (t == 0) g_off[0] = 0;
}
__global__ void k_scatter(const int* __restrict__ ei) {
    int e = blockIdx.x*blockDim.x + threadIdx.x;
    if (e >= ETOT) return;
    int dst = (e < NE) ? ei[NE + e] : (e - NE);
    int src = (e < NE) ? ei[e]      : (e - NE);
    int rank = 0;
    for (int j = 0; j < e; j++) {
        int dj = (j < NE) ? ei[NE + j] : (j - NE);
        if (dj == dst) rank++;
    }
    g_srcs[g_off[dst] + rank] = src;
}

// ---------------- GAT edge-softmax + aggregate ----------------
__global__ __launch_bounds__(64) void k_gat(const float* __restrict__ gatb) {
    int n = blockIdx.x, b = blockIdx.y;
    int off = g_off[n];
    int deg = g_off[n+1] - off;
    float ad = g_ad[b*NN + n];
    int tid = threadIdx.x, lane = tid & 31, w = tid >> 5;
    __shared__ float red[4];

    float lm = NEGINF;
    for (int i = tid; i < deg; i += 64) {
        int s = g_srcs[off + i];
        float e = g_as[b*NN + s] + ad;
        e = (e > 0.f) ? e : 0.2f*e;
        lm = fmaxf(lm, e);
    }
    #pragma unroll
    for (int o = 16; o; o >>= 1) lm = fmaxf(lm, __shfl_xor_sync(0xffffffffu, lm, o));
    if (lane == 0) red[w] = lm;
    __syncthreads();
    float mx = fmaxf(red[0], red[1]);

    float ls = 0.f;
    for (int i = tid; i < deg; i += 64) {
        int s = g_srcs[off + i];
        float e = g_as[b*NN + s] + ad;
        e = (e > 0.f) ? e : 0.2f*e;
        ls += __expf(e - mx);
    }
    #pragma unroll
    for (int o = 16; o; o >>= 1) ls += __shfl_xor_sync(0xffffffffu, ls, o);
    if (lane == 0) red[2 + w] = ls;
    __syncthreads();
    float denom = red[2] + red[3] + 1e-16f;

    float acc = 0.f;
    for (int i = 0; i < deg; i++) {
        int s = g_srcs[off + i];
        float e = g_as[b*NN + s] + ad;
        e = (e > 0.f) ? e : 0.2f*e;
        float wg = __expf(e - mx);
        acc = fmaf(wg, g_h[(long long)(b*NN + s)*GDIM + tid], acc);
    }
    g_g[(long long)(b*NN + n)*GDIM + tid] = acc / denom + gatb[tid];
}

// ---------------- predictor ----------------
__global__ __launch_bounds__(256) void k_pred(
    const float* __restrict__ pW, const float* __restrict__ pb, float* __restrict__ out)
{
    int w = threadIdx.x >> 5, lane = threadIdx.x & 31;
    int row = blockIdx.x*8 + w;
    const float* gr = g_g + (long long)row*GDIM;
    float a = gr[lane], c = gr[32+lane];
    float s0 = a*pW[lane]    + c*pW[32+lane];
    float s1 = a*pW[64+lane] + c*pW[96+lane];
    #pragma unroll
    for (int o = 16; o; o >>= 1) {
        s0 += __shfl_xor_sync(0xffffffffu, s0, o);
        s1 += __shfl_xor_sync(0xffffffffu, s1, o);
    }
    if (lane == 0) {
        out[row*2 + 0] = s0 + pb[0];
        out[row*2 + 1] = s1 + pb[1];
    }
}

// ---------------- host launcher ----------------
extern "C" void kernel_launch(void* const* d_in, const int* in_sizes, int n_in,
                              void* d_out, int out_size)
{
    const float* x       = (const float*)d_in[0];
    const int*   ei      = (const int*)  d_in[1];
    const float* Wqkv    = (const float*)d_in[2];
    const float* bqkv    = (const float*)d_in[3];
    const float* Wo      = (const float*)d_in[4];
    const float* bo      = (const float*)d_in[5];
    const float* g1      = (const float*)d_in[6];
    const float* be1     = (const float*)d_in[7];
    const float* fW1     = (const float*)d_in[8];
    const float* fb1     = (const float*)d_in[9];
    const float* fW2     = (const float*)d_in[10];
    const float* fb2     = (const float*)d_in[11];
    const float* g2      = (const float*)d_in[12];
    const float* be2     = (const float*)d_in[13];
    const float* fcW     = (const float*)d_in[14];
    const float* fcb     = (const float*)d_in[15];
    const float* gatW    = (const float*)d_in[16];
    const float* att_src = (const float*)d_in[17];
    const float* att_dst = (const float*)d_in[18];
    const float* gatb    = (const float*)d_in[19];
    const float* predW   = (const float*)d_in[20];
    const float* predb   = (const float*)d_in[21];
    float* out = (float*)d_out;

    float *xt, *qkv, *attn, *t1, *t2, *feat, *hh;
    cudaGetSymbolAddress((void**)&xt,   g_xt);
    cudaGetSymbolAddress((void**)&qkv,  g_qkv);
    cudaGetSymbolAddress((void**)&attn, g_attn);
    cudaGetSymbolAddress((void**)&t1,   g_t1);
    cudaGetSymbolAddress((void**)&t2,   g_t2);
    cudaGetSymbolAddress((void**)&feat, g_feat);
    cudaGetSymbolAddress((void**)&hh,   g_h);

    const int ATT_SMEM = 2 * 256 * 36 * 4;   // 73728 B
    cudaFuncSetAttribute(k_attn, cudaFuncAttributeMaxDynamicSharedMemorySize, ATT_SMEM);

    // smem: (Ah+Al)=2*128*(KK+8)*2  +  (Wh+Wl)=2*64*(KK+8)*2
    const int SM_K128 = (2*128 + 2*64) * (128+8) * 2;   // 104448
    const int SM_K64  = (2*128 + 2*64) * (64+8)  * 2;   // 55296
    cudaFuncSetAttribute(k_mgemm<128,false,true>,  cudaFuncAttributeMaxDynamicSharedMemorySize, SM_K128);
    cudaFuncSetAttribute(k_mgemm<128,true, true>,  cudaFuncAttributeMaxDynamicSharedMemorySize, SM_K128);
    cudaFuncSetAttribute(k_mgemm<64, false,false>, cudaFuncAttributeMaxDynamicSharedMemorySize, SM_K64);

    k_transpose<<<(NN*BB*DD + 255)/256, 256>>>(x);

    for (int l = 0; l < NL; l++) {
        // QKV: per node [256,128] @ [384,128]^T
        k_mgemm<128,false,true><<<dim3(6, 2, NN), 128, SM_K128>>>(
            xt, (long long)BB*DD,
            Wqkv + (long long)l*3*DD*DD, (long long)NL*3*DD*DD,
            bqkv + (long long)l*3*DD,    (long long)NL*3*DD,
            qkv, (long long)BB*3*DD, 3*DD);
        k_attn<<<dim3(NH, NN), 256, ATT_SMEM>>>();
        // output projection [256,128] @ [128,128]^T
        k_mgemm<128,false,true><<<dim3(2, 2, NN), 128, SM_K128>>>(
            attn, (long long)BB*DD,
            Wo + (long long)l*DD*DD, (long long)NL*DD*DD,
            bo + (long long)l*DD,    (long long)NL*DD,
            t1, (long long)BB*DD, DD);
        k_addln<<<ROWS, 128>>>(xt, t1, g1 + l*DD, be1 + l*DD);
        // FFN1 (relu)
        k_mgemm<128,true,true><<<dim3(2, 2, NN), 128, SM_K128>>>(
            xt, (long long)BB*DD,
            fW1 + (long long)l*DD*DD, (long long)NL*DD*DD,
            fb1 + (long long)l*DD,    (long long)NL*DD,
            t2, (long long)BB*DD, DD);
        // FFN2
        k_mgemm<128,false,true><<<dim3(2, 2, NN), 128, SM_K128>>>(
            t2, (long long)BB*DD,
            fW2 + (long long)l*DD*DD, (long long)NL*DD*DD,
            fb2 + (long long)l*DD,    (long long)NL*DD,
            t1, (long long)BB*DD, DD);
        k_addln<<<ROWS, 128>>>(xt, t1, g2 + l*DD, be2 + l*DD);
    }

    // fc: [51200,128] @ [64,128]^T
    k_mgemm<128,false,true><<<dim3(1, ROWS/128, 1), 128, SM_K128>>>(
        xt, 0, fcW, 0, fcb, 0, feat, 0, FOUT);
    // GAT linear: [51200,64] @ [64,64]^T (no bias)
    k_mgemm<64,false,false><<<dim3(1, ROWS/128, 1), 128, SM_K64>>>(
        feat, 0, gatW, 0, nullptr, 0, hh, 0, GDIM);

    k_attdot<<<ROWS/8, 256>>>(att_src, att_dst);

    k_zero<<<1, 256>>>();
    k_count<<<(ETOT + 255)/256, 256>>>(ei);
    k_scan<<<1, 256>>>();
    k_scatter<<<(ETOT + 255)/256, 256>>>(ei);

    k_gat<<<dim3(NN, BB), 64>>>(gatb);
    k_pred<<<ROWS/8, 256>>>(predW, predb, out);
}

// round 12
// speedup vs baseline: 1.7717x; 1.3019x over previous
#include <cuda_runtime.h>
#include <cuda_bf16.h>
#include <cstdint>

#define NN    200
#define DD    128
#define BB    256
#define NH    4
#define DH    32
#define NL    2
#define FOUT  64
#define GDIM  64
#define NE    1600
#define ETOT  1800
#define ROWS  (NN*BB)          // 51200
#define NEGINF (-3.4e38f)
#define LOG2E 1.4426950408889634f

// ---------------- scratch (static device memory; no allocation) ----------------
__device__ float g_xt  [NN*BB*DD];
__device__ float g_qkv [NN*BB*3*DD];
__device__ float g_attn[NN*BB*DD];
__device__ float g_t1  [NN*BB*DD];
__device__ float g_t2  [NN*BB*DD];
__device__ float g_feat[ROWS*FOUT];
__device__ float g_h   [ROWS*GDIM];
__device__ float g_as  [ROWS];
__device__ float g_ad  [ROWS];
__device__ float g_g   [ROWS*GDIM];
__device__ int   g_deg [NN+1];
__device__ int   g_off [NN+1];
__device__ int   g_srcs[ETOT];

__device__ __forceinline__ uint32_t smem_u32(const void* p) {
    uint32_t a;
    asm("{ .reg .u64 t; cvta.to.shared.u64 t, %1; cvt.u32.u64 %0, t; }" : "=r"(a) : "l"(p));
    return a;
}

// split one float4 into bf16 hi/lo pairs (packed 2x per u32)
__device__ __forceinline__ void cvt_split4(float4 v, uint2& hp, uint2& lp) {
    __nv_bfloat16 hx = __float2bfloat16(v.x), hy = __float2bfloat16(v.y);
    __nv_bfloat16 hz = __float2bfloat16(v.z), hw = __float2bfloat16(v.w);
    __nv_bfloat16 lx = __float2bfloat16(v.x - __bfloat162float(hx));
    __nv_bfloat16 ly = __float2bfloat16(v.y - __bfloat162float(hy));
    __nv_bfloat16 lz = __float2bfloat16(v.z - __bfloat162float(hz));
    __nv_bfloat16 lw = __float2bfloat16(v.w - __bfloat162float(hw));
    hp.x = ((uint32_t)__bfloat16_as_ushort(hy) << 16) | __bfloat16_as_ushort(hx);
    hp.y = ((uint32_t)__bfloat16_as_ushort(hw) << 16) | __bfloat16_as_ushort(hz);
    lp.x = ((uint32_t)__bfloat16_as_ushort(ly) << 16) | __bfloat16_as_ushort(lx);
    lp.y = ((uint32_t)__bfloat16_as_ushort(lw) << 16) | __bfloat16_as_ushort(lz);
}

// pack two fp32 -> bf16x2 hi and residual-lo
__device__ __forceinline__ void pk_hl(float x, float y, uint32_t& h, uint32_t& l) {
    __nv_bfloat16 hx = __float2bfloat16(x), hy = __float2bfloat16(y);
    __nv_bfloat16 lx = __float2bfloat16(x - __bfloat162float(hx));
    __nv_bfloat16 ly = __float2bfloat16(y - __bfloat162float(hy));
    h = ((uint32_t)__bfloat16_as_ushort(hy) << 16) | __bfloat16_as_ushort(hx);
    l = ((uint32_t)__bfloat16_as_ushort(ly) << 16) | __bfloat16_as_ushort(lx);
}

// FMA-pipe exp2 (no MUFU). |err| ~1.4e-7 for x<=0. Clamps below -120.
__device__ __forceinline__ float fexp2(float x) {
    x = fmaxf(x, -120.f);
    float t = x + 12582912.f;                       // round-to-nearest int
    int n = __float_as_int(t) - 0x4B400000;
    float r = x - (t - 12582912.f);                 // r in [-0.5, 0.5]
    float p = 1.54035304e-4f;
    p = fmaf(p, r, 1.33335581e-3f);
    p = fmaf(p, r, 9.61812911e-3f);
    p = fmaf(p, r, 5.55041086e-2f);
    p = fmaf(p, r, 2.40226507e-1f);
    p = fmaf(p, r, 6.93147182e-1f);
    p = fmaf(p, r, 1.0f);
    return p * __int_as_float((n + 127) << 23);
}

#define MMA16816(ACC, A0,A1,A2,A3, B0,B1) \
    asm volatile( \
        "mma.sync.aligned.m16n8k16.row.col.f32.bf16.bf16.f32 " \
        "{%0,%1,%2,%3}, {%4,%5,%6,%7}, {%8,%9}, {%0,%1,%2,%3};" \
        : "+f"((ACC)[0]), "+f"((ACC)[1]), "+f"((ACC)[2]), "+f"((ACC)[3]) \
        : "r"(A0), "r"(A1), "r"(A2), "r"(A3), "r"(B0), "r"(B1))

// =================== HMMA GEMM: C[128 x 64 tile] = A @ W^T (+bias)(+relu) ===================
// bf16 2-term split, 3 accumulation passes fused into the k-loop (fragments loaded once).
template<int KK, bool RELU, bool HASB>
__global__ __launch_bounds__(128) void k_mgemm(
    const float* __restrict__ A, long long sA,
    const float* __restrict__ W, long long sW,
    const float* __restrict__ bias, long long sB,
    float* __restrict__ C, long long sC, int N)
{
    constexpr int LDA = KK + 8;
    constexpr int K4 = KK / 4;

    extern __shared__ char sm[];
    __nv_bfloat16* Ah = (__nv_bfloat16*)sm;
    __nv_bfloat16* Al = Ah + 128 * LDA;
    __nv_bfloat16* Wh = Al + 128 * LDA;
    __nv_bfloat16* Wl = Wh + 64 * LDA;

    const int tid = threadIdx.x;
    const int bz = blockIdx.z;
    const int m0 = blockIdx.y * 128;
    const int n0 = blockIdx.x * 64;

    A += (long long)bz * sA;
    W += (long long)bz * sW;
    C += (long long)bz * sC;
    if (HASB) bias += (long long)bz * sB;

    {
        const float* Ag = A + (long long)m0 * KK;
        #pragma unroll
        for (int c = tid; c < 128 * K4; c += 128) {
            int row = c / K4, k4 = (c % K4) * 4;
            float4 v = *(const float4*)(Ag + (long long)row * KK + k4);
            uint2 hp, lp;
            cvt_split4(v, hp, lp);
            *(uint2*)&Ah[row * LDA + k4] = hp;
            *(uint2*)&Al[row * LDA + k4] = lp;
        }
    }
    {
        const float* Wg = W + (long long)n0 * KK;
        #pragma unroll
        for (int c = tid; c < 64 * K4; c += 128) {
            int row = c / K4, k4 = (c % K4) * 4;
            float4 v = *(const float4*)(Wg + (long long)row * KK + k4);
            uint2 hp, lp;
            cvt_split4(v, hp, lp);
            *(uint2*)&Wh[row * LDA + k4] = hp;
            *(uint2*)&Wl[row * LDA + k4] = lp;
        }
    }
    __syncthreads();

    const int wid = tid >> 5, lane = tid & 31;
    const int mw = wid * 32;

    float acc[2][8][4];
    #pragma unroll
    for (int t = 0; t < 2; t++)
        #pragma unroll
        for (int j = 0; j < 8; j++)
            #pragma unroll
            for (int q = 0; q < 4; q++) acc[t][j][q] = 0.f;

    uint32_t sAh = smem_u32(Ah), sAl = smem_u32(Al);
    uint32_t sWh = smem_u32(Wh), sWl = smem_u32(Wl);

    const int a_row = lane & 15;
    const int a_col = (lane >> 4) * 8;
    const int b_row = lane & 7;
    const int b_col = ((lane >> 3) & 1) * 8;

    #pragma unroll
    for (int k0 = 0; k0 < KK; k0 += 16) {
        uint32_t ah[2][4], al[2][4];
        #pragma unroll
        for (int t = 0; t < 2; t++) {
            uint32_t off = (uint32_t)(((mw + t*16 + a_row) * LDA + k0 + a_col) * 2);
            asm volatile("ldmatrix.sync.aligned.m8n8.x4.shared.b16 {%0,%1,%2,%3}, [%4];"
                : "=r"(ah[t][0]), "=r"(ah[t][1]), "=r"(ah[t][2]), "=r"(ah[t][3]) : "r"(sAh + off));
            asm volatile("ldmatrix.sync.aligned.m8n8.x4.shared.b16 {%0,%1,%2,%3}, [%4];"
                : "=r"(al[t][0]), "=r"(al[t][1]), "=r"(al[t][2]), "=r"(al[t][3]) : "r"(sAl + off));
        }
        #pragma unroll
        for (int j = 0; j < 8; j++) {
            uint32_t off = (uint32_t)(((j*8 + b_row) * LDA + k0 + b_col) * 2);
            uint32_t bh0, bh1, bl0, bl1;
            asm volatile("ldmatrix.sync.aligned.m8n8.x2.shared.b16 {%0,%1}, [%2];"
                : "=r"(bh0), "=r"(bh1) : "r"(sWh + off));
            asm volatile("ldmatrix.sync.aligned.m8n8.x2.shared.b16 {%0,%1}, [%2];"
                : "=r"(bl0), "=r"(bl1) : "r"(sWl + off));
            #pragma unroll
            for (int t = 0; t < 2; t++) {
                MMA16816(acc[t][j], ah[t][0],ah[t][1],ah[t][2],ah[t][3], bh0,bh1);
                MMA16816(acc[t][j], ah[t][0],ah[t][1],ah[t][2],ah[t][3], bl0,bl1);
                MMA16816(acc[t][j], al[t][0],al[t][1],al[t][2],al[t][3], bh0,bh1);
            }
        }
    }

    const int r0 = m0 + mw + (lane >> 2);
    const int nc = (lane & 3) * 2;
    #pragma unroll
    for (int j = 0; j < 8; j++) {
        int n = n0 + j*8 + nc;
        float b0v = 0.f, b1v = 0.f;
        if (HASB) { b0v = bias[n]; b1v = bias[n+1]; }
        #pragma unroll
        for (int t = 0; t < 2; t++) {
            float v0 = acc[t][j][0] + b0v, v1 = acc[t][j][1] + b1v;
            float v2 = acc[t][j][2] + b0v, v3 = acc[t][j][3] + b1v;
            if (RELU) {
                v0 = fmaxf(v0, 0.f); v1 = fmaxf(v1, 0.f);
                v2 = fmaxf(v2, 0.f); v3 = fmaxf(v3, 0.f);
            }
            long long r = r0 + t*16;
            *(float2*)&C[r * N + n]       = make_float2(v0, v1);
            *(float2*)&C[(r + 8) * N + n] = make_float2(v2, v3);
        }
    }
}

// =================== flash-style HMMA attention: CTA per (head, node) ===================
// 256 threads = 8 warps; warp w owns query rows [w*32, w*32+32). Keys processed in 4 blocks of 64.
// Q,K in smem as hi/lo bf16 [256][40]; V transposed hi/lo [32][264].
__global__ __launch_bounds__(256) void k_fattn() {
    extern __shared__ char sm[];
    __nv_bfloat16* Qh  = (__nv_bfloat16*)sm;
    __nv_bfloat16* Ql  = Qh + 256*40;
    __nv_bfloat16* Kh  = Ql + 256*40;
    __nv_bfloat16* Kl  = Kh + 256*40;
    __nv_bfloat16* Vth = Kl + 256*40;
    __nv_bfloat16* Vtl = Vth + 32*264;

    const int h = blockIdx.x, n = blockIdx.y;
    const int tid = threadIdx.x;
    const int w = tid >> 5, lane = tid & 31;

    // ---- fill: one row per thread ----
    {
        const float* base = g_qkv + ((long long)n*BB + tid)*384 + h*DH;
        #pragma unroll
        for (int d4 = 0; d4 < 8; d4++) {
            uint2 hp, lp;
            float4 q = *(const float4*)(base + d4*4);
            cvt_split4(q, hp, lp);
            *(uint2*)&Qh[tid*40 + d4*4] = hp;
            *(uint2*)&Ql[tid*40 + d4*4] = lp;
            float4 k = *(const float4*)(base + 128 + d4*4);
            cvt_split4(k, hp, lp);
            *(uint2*)&Kh[tid*40 + d4*4] = hp;
            *(uint2*)&Kl[tid*40 + d4*4] = lp;
            float4 v = *(const float4*)(base + 256 + d4*4);
            float vv[4] = {v.x, v.y, v.z, v.w};
            #pragma unroll
            for (int u = 0; u < 4; u++) {
                __nv_bfloat16 hv = __float2bfloat16(vv[u]);
                __nv_bfloat16 lv = __float2bfloat16(vv[u] - __bfloat162float(hv));
                Vth[(d4*4+u)*264 + tid] = hv;
                Vtl[(d4*4+u)*264 + tid] = lv;
            }
        }
    }
    __syncthreads();

    uint32_t sQh = smem_u32(Qh), sQl = smem_u32(Ql);
    uint32_t sKh = smem_u32(Kh), sKl = smem_u32(Kl);
    uint32_t sVh = smem_u32(Vth), sVl = smem_u32(Vtl);

    // ---- Q fragments (held in registers) ----
    uint32_t qh[2][2][4], ql[2][2][4];
    {
        const int a_row = lane & 15, a_col = (lane >> 4) * 8;
        #pragma unroll
        for (int mt = 0; mt < 2; mt++)
            #pragma unroll
            for (int kt = 0; kt < 2; kt++) {
                uint32_t off = (uint32_t)(((w*32 + mt*16 + a_row)*40 + kt*16 + a_col) * 2);
                asm volatile("ldmatrix.sync.aligned.m8n8.x4.shared.b16 {%0,%1,%2,%3}, [%4];"
                    : "=r"(qh[mt][kt][0]), "=r"(qh[mt][kt][1]), "=r"(qh[mt][kt][2]), "=r"(qh[mt][kt][3])
                    : "r"(sQh + off));
                asm volatile("ldmatrix.sync.aligned.m8n8.x4.shared.b16 {%0,%1,%2,%3}, [%4];"
                    : "=r"(ql[mt][kt][0]), "=r"(ql[mt][kt][1]), "=r"(ql[mt][kt][2]), "=r"(ql[mt][kt][3])
                    : "r"(sQl + off));
            }
    }

    float O[2][4][4];
    float M[2][2], L[2][2];
    #pragma unroll
    for (int mt = 0; mt < 2; mt++) {
        M[mt][0] = M[mt][1] = -1e30f;
        L[mt][0] = L[mt][1] = 0.f;
        #pragma unroll
        for (int j2 = 0; j2 < 4; j2++)
            #pragma unroll
            for (int q = 0; q < 4; q++) O[mt][j2][q] = 0.f;
    }

    const float scl = 0.17677669529663687f;  // 1/sqrt(32)
    const int b_row = lane & 7, b_col = ((lane >> 3) & 1) * 8;

    for (int kb = 0; kb < 4; kb++) {
        // ---- S = Q @ K^T (3-pass split) ----
        float S[2][8][4];
        #pragma unroll
        for (int mt = 0; mt < 2; mt++)
            #pragma unroll
            for (int j = 0; j < 8; j++)
                #pragma unroll
                for (int q = 0; q < 4; q++) S[mt][j][q] = 0.f;

        #pragma unroll
        for (int j = 0; j < 8; j++) {
            #pragma unroll
            for (int kt = 0; kt < 2; kt++) {
                uint32_t off = (uint32_t)(((kb*64 + j*8 + b_row)*40 + kt*16 + b_col) * 2);
                uint32_t kh0, kh1, kl0, kl1;
                asm volatile("ldmatrix.sync.aligned.m8n8.x2.shared.b16 {%0,%1}, [%2];"
                    : "=r"(kh0), "=r"(kh1) : "r"(sKh + off));
                asm volatile("ldmatrix.sync.aligned.m8n8.x2.shared.b16 {%0,%1}, [%2];"
                    : "=r"(kl0), "=r"(kl1) : "r"(sKl + off));
                #pragma unroll
                for (int mt = 0; mt < 2; mt++) {
                    MMA16816(S[mt][j], qh[mt][kt][0],qh[mt][kt][1],qh[mt][kt][2],qh[mt][kt][3], kh0,kh1);
                    MMA16816(S[mt][j], qh[mt][kt][0],qh[mt][kt][1],qh[mt][kt][2],qh[mt][kt][3], kl0,kl1);
                    MMA16816(S[mt][j], ql[mt][kt][0],ql[mt][kt][1],ql[mt][kt][2],ql[mt][kt][3], kh0,kh1);
                }
            }
        }

        // ---- online softmax on fragments ----
        #pragma unroll
        for (int mt = 0; mt < 2; mt++) {
            float mx0 = -1e30f, mx1 = -1e30f;
            #pragma unroll
            for (int j = 0; j < 8; j++) {
                S[mt][j][0] *= scl; S[mt][j][1] *= scl;
                S[mt][j][2] *= scl; S[mt][j][3] *= scl;
                mx0 = fmaxf(mx0, fmaxf(S[mt][j][0], S[mt][j][1]));
                mx1 = fmaxf(mx1, fmaxf(S[mt][j][2], S[mt][j][3]));
            }
            mx0 = fmaxf(mx0, __shfl_xor_sync(0xffffffffu, mx0, 1));
            mx0 = fmaxf(mx0, __shfl_xor_sync(0xffffffffu, mx0, 2));
            mx1 = fmaxf(mx1, __shfl_xor_sync(0xffffffffu, mx1, 1));
            mx1 = fmaxf(mx1, __shfl_xor_sync(0xffffffffu, mx1, 2));
            float nM0 = fmaxf(M[mt][0], mx0), nM1 = fmaxf(M[mt][1], mx1);
            float f0 = fexp2((M[mt][0] - nM0) * LOG2E);
            float f1 = fexp2((M[mt][1] - nM1) * LOG2E);
            M[mt][0] = nM0; M[mt][1] = nM1;
            float s0 = 0.f, s1 = 0.f;
            #pragma unroll
            for (int j = 0; j < 8; j++) {
                float p0 = fexp2((S[mt][j][0] - nM0) * LOG2E);
                float p1 = fexp2((S[mt][j][1] - nM0) * LOG2E);
                float p2 = fexp2((S[mt][j][2] - nM1) * LOG2E);
                float p3 = fexp2((S[mt][j][3] - nM1) * LOG2E);
                S[mt][j][0] = p0; S[mt][j][1] = p1; S[mt][j][2] = p2; S[mt][j][3] = p3;
                s0 += p0 + p1; s1 += p2 + p3;
            }
            L[mt][0] = L[mt][0] * f0 + s0;
            L[mt][1] = L[mt][1] * f1 + s1;
            #pragma unroll
            for (int j2 = 0; j2 < 4; j2++) {
                O[mt][j2][0] *= f0; O[mt][j2][1] *= f0;
                O[mt][j2][2] *= f1; O[mt][j2][3] *= f1;
            }
        }

        // ---- O += P @ V (3-pass split; P frags packed from S accs) ----
        #pragma unroll
        for (int kt2 = 0; kt2 < 4; kt2++) {
            uint32_t pah[2][4], pal[2][4];
            #pragma unroll
            for (int mt = 0; mt < 2; mt++) {
                int j0 = 2*kt2, j1 = j0 + 1;
                pk_hl(S[mt][j0][0], S[mt][j0][1], pah[mt][0], pal[mt][0]);
                pk_hl(S[mt][j0][2], S[mt][j0][3], pah[mt][1], pal[mt][1]);
                pk_hl(S[mt][j1][0], S[mt][j1][1], pah[mt][2], pal[mt][2]);
                pk_hl(S[mt][j1][2], S[mt][j1][3], pah[mt][3], pal[mt][3]);
            }
            #pragma unroll
            for (int j2 = 0; j2 < 4; j2++) {
                uint32_t off = (uint32_t)(((j2*8 + b_row)*264 + kb*64 + kt2*16 + b_col) * 2);
                uint32_t vh0, vh1, vl0, vl1;
                asm volatile("ldmatrix.sync.aligned.m8n8.x2.shared.b16 {%0,%1}, [%2];"
                    : "=r"(vh0), "=r"(vh1) : "r"(sVh + off));
                asm volatile("ldmatrix.sync.aligned.m8n8.x2.shared.b16 {%0,%1}, [%2];"
                    : "=r"(vl0), "=r"(vl1) : "r"(sVl + off));
                #pragma unroll
                for (int mt = 0; mt < 2; mt++) {
                    MMA16816(O[mt][j2], pah[mt][0],pah[mt][1],pah[mt][2],pah[mt][3], vh0,vh1);
                    MMA16816(O[mt][j2], pah[mt][0],pah[mt][1],pah[mt][2],pah[mt][3], vl0,vl1);
                    MMA16816(O[mt][j2], pal[mt][0],pal[mt][1],pal[mt][2],pal[mt][3], vh0,vh1);
                }
            }
        }
    }

    // ---- normalize and write ----
    #pragma unroll
    for (int mt = 0; mt < 2; mt++) {
        float l0 = L[mt][0];
        l0 += __shfl_xor_sync(0xffffffffu, l0, 1);
        l0 += __shfl_xor_sync(0xffffffffu, l0, 2);
        float l1 = L[mt][1];
        l1 += __shfl_xor_sync(0xffffffffu, l1, 1);
        l1 += __shfl_xor_sync(0xffffffffu, l1, 2);
        float inv0 = 1.f / l0, inv1 = 1.f / l1;
        int qrow = w*32 + mt*16 + (lane >> 2);
        int col  = h*DH + (lane & 3)*2;
        #pragma unroll
        for (int j2 = 0; j2 < 4; j2++) {
            float* p0 = g_attn + ((long long)n*BB + qrow)*128 + col + j2*8;
            float* p1 = g_attn + ((long long)n*BB + qrow + 8)*128 + col + j2*8;
            *(float2*)p0 = make_float2(O[mt][j2][0]*inv0, O[mt][j2][1]*inv0);
            *(float2*)p1 = make_float2(O[mt][j2][2]*inv1, O[mt][j2][3]*inv1);
        }
    }
}

// ---------------- transpose x[b][n][d] -> g_xt[n][b][d] ----------------
__global__ void k_transpose(const float* __restrict__ x) {
    int i = blockIdx.x * blockDim.x + threadIdx.x;
    if (i >= NN*BB*DD) return;
    int d = i & 127;
    int b = (i >> 7) & 255;
    int n = i >> 15;
    g_xt[i] = x[((b*NN + n) << 7) + d];
}

// ---------------- residual add + LayerNorm over D=128 ----------------
__global__ __launch_bounds__(128) void k_addln(
    float* __restrict__ x, const float* __restrict__ r,
    const float* __restrict__ gamma, const float* __restrict__ beta)
{
    int row = blockIdx.x;
    int n = row >> 8;
    int t = threadIdx.x;
    long long idx = (long long)row*128 + t;
    float v = x[idx] + r[idx];
    float s = v, s2 = v*v;
    #pragma unroll
    for (int o = 16; o; o >>= 1) {
        s  += __shfl_xor_sync(0xffffffffu, s,  o);
        s2 += __shfl_xor_sync(0xffffffffu, s2, o);
    }
    __shared__ float red[8];
    int w = t >> 5;
    if ((t & 31) == 0) { red[w] = s; red[4+w] = s2; }
    __syncthreads();
    s  = red[0]+red[1]+red[2]+red[3];
    s2 = red[4]+red[5]+red[6]+red[7];
    float mean = s * (1.f/128.f);
    float var  = s2 * (1.f/128.f) - mean*mean;
    float rinv = rsqrtf(var + 1e-5f);
    x[idx] = (v - mean) * rinv * gamma[n*(NL*DD) + t] + beta[n*(NL*DD) + t];
}

// ---------------- attention-coefficient dots ----------------
__global__ __launch_bounds__(256) void k_attdot(
    const float* __restrict__ asv, const float* __restrict__ adv)
{
    int w = threadIdx.x >> 5, lane = threadIdx.x & 31;
    int row = blockIdx.x*8 + w;
    const float* hr = g_h + (long long)row*GDIM;
    float h1 = hr[lane], h2 = hr[32+lane];
    float s = h1*asv[lane] + h2*asv[32+lane];
    float d = h1*adv[lane] + h2*adv[32+lane];
    #pragma unroll
    for (int o = 16; o; o >>= 1) {
        s += __shfl_xor_sync(0xffffffffu, s, o);
        d += __shfl_xor_sync(0xffffffffu, d, o);
    }
    if (lane == 0) { g_as[row] = s; g_ad[row] = d; }
}

// ---------------- CSR build (deterministic) ----------------
__global__ void k_zero() {
    int i = blockIdx.x*blockDim.x + threadIdx.x;
    if (i <= NN) g_deg[i] = 0;
}
__global__ void k_count(const int* __restrict__ ei) {
    int e = blockIdx.x*blockDim.x + threadIdx.x;
    if (e >= ETOT) return;
    int dst = (e < NE) ? ei[NE + e] : (e - NE);
    atomicAdd(&g_deg[dst], 1);
}
__global__ void k_scan() {
    __shared__ int s[256];
    int t = threadIdx.x;
    int v = (t < NN) ? g_deg[t] : 0;
    s[t] = v;
    __syncthreads();
    for (int o = 1; o < 256; o <<= 1) {
        int a = (t >= o) ? s[t-o] : 0;
        __syncthreads();
        s[t] += a;
        __syncthreads();
    }
    if (t < NN) g_off[t+1] = s[t];
    if (t == 0) g_off[0] = 0;
}
__global__ void k_scatter(const int* __restrict__ ei) {
    int e = blockIdx.x*blockDim.x + threadIdx.x;
    if (e >= ETOT) return;
    int dst = (e < NE) ? ei[NE + e] : (e - NE);
    int src = (e < NE) ? ei[e]      : (e - NE);
    int rank = 0;
    for (int j = 0; j < e; j++) {
        int dj = (j < NE) ? ei[NE + j] : (j - NE);
        if (dj == dst) rank++;
    }
    g_srcs[g_off[dst] + rank] = src;
}

// ---------------- GAT edge-softmax + aggregate ----------------
__global__ __launch_bounds__(64) void k_gat(const float* __restrict__ gatb) {
    int n = blockIdx.x, b = blockIdx.y;
    int off = g_off[n];
    int deg = g_off[n+1] - off;
    float ad = g_ad[b*NN + n];
    int tid = threadIdx.x, lane = tid & 31, w = tid >> 5;
    __shared__ float red[4];

    float lm = NEGINF;
    for (int i = tid; i < deg; i += 64) {
        int s = g_srcs[off + i];
        float e = g_as[b*NN + s] + ad;
        e = (e > 0.f) ? e : 0.2f*e;
        lm = fmaxf(lm, e);
    }
    #pragma unroll
    for (int o = 16; o; o >>= 1) lm = fmaxf(lm, __shfl_xor_sync(0xffffffffu, lm, o));
    if (lane == 0) red[w] = lm;
    __syncthreads();
    float mx = fmaxf(red[0], red[1]);

    float ls = 0.f;
    for (int i = tid; i < deg; i += 64) {
        int s = g_srcs[off + i];
        float e = g_as[b*NN + s] + ad;
        e = (e > 0.f) ? e : 0.2f*e;
        ls += __expf(e - mx);
    }
    #pragma unroll
    for (int o = 16; o; o >>= 1) ls += __shfl_xor_sync(0xffffffffu, ls, o);
    if (lane == 0) red[2 + w] = ls;
    __syncthreads();
    float denom = red[2] + red[3] + 1e-16f;

    float acc = 0.f;
    for (int i = 0; i < deg; i++) {
        int s = g_srcs[off + i];
        float e = g_as[b*NN + s] + ad;
        e = (e > 0.f) ? e : 0.2f*e;
        float wg = __expf(e - mx);
        acc = fmaf(wg, g_h[(long long)(b*NN + s)*GDIM + tid], acc);
    }
    g_g[(long long)(b*NN + n)*GDIM + tid] = acc / denom + gatb[tid];
}

// ---------------- predictor ----------------
__global__ __launch_bounds__(256) void k_pred(
    const float* __restrict__ pW, const float* __restrict__ pb, float* __restrict__ out)
{
    int w = threadIdx.x >> 5, lane = threadIdx.x & 31;
    int row = blockIdx.x*8 + w;
    const float* gr = g_g + (long long)row*GDIM;
    float a = gr[lane], c = gr[32+lane];
    float s0 = a*pW[lane]    + c*pW[32+lane];
    float s1 = a*pW[64+lane] + c*pW[96+lane];
    #pragma unroll
    for (int o = 16; o; o >>= 1) {
        s0 += __shfl_xor_sync(0xffffffffu, s0, o);
        s1 += __shfl_xor_sync(0xffffffffu, s1, o);
    }
    if (lane == 0) {
        out[row*2 + 0] = s0 + pb[0];
        out[row*2 + 1] = s1 + pb[1];
    }
}

// ---------------- host launcher ----------------
extern "C" void kernel_launch(void* const* d_in, const int* in_sizes, int n_in,
                              void* d_out, int out_size)
{
    const float* x       = (const float*)d_in[0];
    const int*   ei      = (const int*)  d_in[1];
    const float* Wqkv    = (const float*)d_in[2];
    const float* bqkv    = (const float*)d_in[3];
    const float* Wo      = (const float*)d_in[4];
    const float* bo      = (const float*)d_in[5];
    const float* g1      = (const float*)d_in[6];
    const float* be1     = (const float*)d_in[7];
    const float* fW1     = (const float*)d_in[8];
    const float* fb1     = (const float*)d_in[9];
    const float* fW2     = (const float*)d_in[10];
    const float* fb2     = (const float*)d_in[11];
    const float* g2      = (const float*)d_in[12];
    const float* be2     = (const float*)d_in[13];
    const float* fcW     = (const float*)d_in[14];
    const float* fcb     = (const float*)d_in[15];
    const float* gatW    = (const float*)d_in[16];
    const float* att_src = (const float*)d_in[17];
    const float* att_dst = (const float*)d_in[18];
    const float* gatb    = (const float*)d_in[19];
    const float* predW   = (const float*)d_in[20];
    const float* predb   = (const float*)d_in[21];
    float* out = (float*)d_out;

    float *xt, *qkv, *attn, *t1, *t2, *feat, *hh;
    cudaGetSymbolAddress((void**)&xt,   g_xt);
    cudaGetSymbolAddress((void**)&qkv,  g_qkv);
    cudaGetSymbolAddress((void**)&attn, g_attn);
    cudaGetSymbolAddress((void**)&t1,   g_t1);
    cudaGetSymbolAddress((void**)&t2,   g_t2);
    cudaGetSymbolAddress((void**)&feat, g_feat);
    cudaGetSymbolAddress((void**)&hh,   g_h);

    // k_fattn smem: 4 * 256*40*2 + 2 * 32*264*2 = 81920 + 33792
    const int FATT_SMEM = 4*256*40*2 + 2*32*264*2;   // 115712
    cudaFuncSetAttribute(k_fattn, cudaFuncAttributeMaxDynamicSharedMemorySize, FATT_SMEM);

    const int SM_K128 = (2*128 + 2*64) * (128+8) * 2;   // 104448
    const int SM_K64  = (2*128 + 2*64) * (64+8)  * 2;   // 55296
    cudaFuncSetAttribute(k_mgemm<128,false,true>,  cudaFuncAttributeMaxDynamicSharedMemorySize, SM_K128);
    cudaFuncSetAttribute(k_mgemm<128,true, true>,  cudaFuncAttributeMaxDynamicSharedMemorySize, SM_K128);
    cudaFuncSetAttribute(k_mgemm<64, false,false>, cudaFuncAttributeMaxDynamicSharedMemorySize, SM_K64);

    k_transpose<<<(NN*BB*DD + 255)/256, 256>>>(x);

    for (int l = 0; l < NL; l++) {
        k_mgemm<128,false,true><<<dim3(6, 2, NN), 128, SM_K128>>>(
            xt, (long long)BB*DD,
            Wqkv + (long long)l*3*DD*DD, (long long)NL*3*DD*DD,
            bqkv + (long long)l*3*DD,    (long long)NL*3*DD,
            qkv, (long long)BB*3*DD, 3*DD);
        k_fattn<<<dim3(NH, NN), 256, FATT_SMEM>>>();
        k_mgemm<128,false,true><<<dim3(2, 2, NN), 128, SM_K128>>>(
            attn, (long long)BB*DD,
            Wo + (long long)l*DD*DD, (long long)NL*DD*DD,
            bo + (long long)l*DD,    (long long)NL*DD,
            t1, (long long)BB*DD, DD);
        k_addln<<<ROWS, 128>>>(xt, t1, g1 + l*DD, be1 + l*DD);
        k_mgemm<128,true,true><<<dim3(2, 2, NN), 128, SM_K128>>>(
            xt, (long long)BB*DD,
            fW1 + (long long)l*DD*DD, (long long)NL*DD*DD,
            fb1 + (long long)l*DD,    (long long)NL*DD,
            t2, (long long)BB*DD, DD);
        k_mgemm<128,false,true><<<dim3(2, 2, NN), 128, SM_K128>>>(
            t2, (long long)BB*DD,
            fW2 + (long long)l*DD*DD, (long long)NL*DD*DD,
            fb2 + (long long)l*DD,    (long long)NL*DD,
            t1, (long long)BB*DD, DD);
        k_addln<<<ROWS, 128>>>(xt, t1, g2 + l*DD, be2 + l*DD);
    }

    k_mgemm<128,false,true><<<dim3(1, ROWS/128, 1), 128, SM_K128>>>(
        xt, 0, fcW, 0, fcb, 0, feat, 0, FOUT);
    k_mgemm<64,false,false><<<dim3(1, ROWS/128, 1), 128, SM_K64>>>(
        feat, 0, gatW, 0, nullptr, 0, hh, 0, GDIM);

    k_attdot<<<ROWS/8, 256>>>(att_src, att_dst);

    k_zero<<<1, 256>>>();
    k_count<<<(ETOT + 255)/256, 256>>>(ei);
    k_scan<<<1, 256>>>();
    k_scatter<<<(ETOT + 255)/256, 256>>>(ei);

    k_gat<<<dim3(NN, BB), 64>>>(gatb);
    k_pred<<<ROWS/8, 256>>>(predW, predb, out);
}